// round 3
// baseline (speedup 1.0000x reference)
#include <cuda_runtime.h>
#include <cuda_bf16.h>
#include <math.h>

#define N_NODES 100000
#define N_EDGES 1600000
#define ET      (N_EDGES + N_NODES)   // with self-loops
#define N_GRAPHS 256
#define IN_DIM  480
#define HID     128
#define HEADS   4
#define HEAD_DIM 32
#define LAYERS  3
#define NEG_SLOPE 0.2f
#define LN_EPS 1e-5f

// ---------------- scratch (device globals; re-initialized every call) -------
__device__ float    g_h   [N_NODES * HID];   // current features / residual
__device__ float    g_h2  [N_NODES * HID];   // projected features per layer
__device__ float    g_agg [N_NODES * HID];   // aggregation accumulator
__device__ float    g_asrc[N_NODES * HEADS];
__device__ float    g_adst[N_NODES * HEADS];
__device__ float    g_e   [ET * HEADS];      // edge logits, then exp values
__device__ unsigned g_emax[N_NODES * HEADS]; // order-encoded float max
__device__ float    g_den [N_NODES * HEADS];
__device__ float    g_psum[N_GRAPHS * HID];
__device__ int      g_pcnt[N_GRAPHS];

// order-preserving float<->uint encoding for atomicMax on floats
__device__ __forceinline__ unsigned fenc(float f) {
    int i = __float_as_int(f);
    return i >= 0 ? ((unsigned)i | 0x80000000u) : ~(unsigned)i;
}
__device__ __forceinline__ float fdec(unsigned u) {
    return (u & 0x80000000u) ? __int_as_float((int)(u & 0x7fffffffu))
                             : __uint_as_float(~u);
}

// sm_90+ vector reduction: one 16B L2 atomic instead of 4 scalar atomics
__device__ __forceinline__ void redAdd4(float* addr, float4 v) {
    asm volatile("red.global.add.v4.f32 [%0], {%1,%2,%3,%4};"
                 :: "l"(addr), "f"(v.x), "f"(v.y), "f"(v.z), "f"(v.w)
                 : "memory");
}

// ---------------- GEMM: C[M,128] = A[M,K] @ B[K,128] (+bias, relu) ----------
// BM=64, BN=128(full), BK=16, 256 threads. Warp w handles rows w*8..w*8+7;
// A-tile reads are warp-uniform broadcasts, B reads are 128-bit conflict-free.
// MODE 0: A = input x, C = g_h, bias+relu.  MODE 1: A = g_h, C = g_h2, plain.
template <int MODE>
__global__ __launch_bounds__(256) void gemm128_kernel(
    const float* __restrict__ Ain, const float* __restrict__ B,
    const float* __restrict__ bias, int M, int K)
{
    const float* A = (MODE == 0) ? Ain : g_h;
    float*       C = (MODE == 0) ? g_h : g_h2;

    __shared__ float As[64][16];
    __shared__ float Bs[16][128];
    const int t = threadIdx.x;
    const int warp = t >> 5, lane = t & 31;
    const int bm = blockIdx.x * 64;

    float acc[8][4];
#pragma unroll
    for (int i = 0; i < 8; i++) { acc[i][0]=0.f; acc[i][1]=0.f; acc[i][2]=0.f; acc[i][3]=0.f; }

    for (int kt = 0; kt < K; kt += 16) {
        {
            int row = t >> 2, c4 = (t & 3) * 4;
            float4 v = make_float4(0.f, 0.f, 0.f, 0.f);
            if (bm + row < M)
                v = *(const float4*)&A[(size_t)(bm + row) * K + kt + c4];
            As[row][c4+0] = v.x; As[row][c4+1] = v.y;
            As[row][c4+2] = v.z; As[row][c4+3] = v.w;
        }
#pragma unroll
        for (int j = 0; j < 2; j++) {
            int idx = t + j * 256;
            int row = idx >> 5, c4 = (idx & 31) * 4;
            *(float4*)&Bs[row][c4] = *(const float4*)&B[(size_t)(kt + row) * 128 + c4];
        }
        __syncthreads();
#pragma unroll
        for (int k = 0; k < 16; k++) {
            float4 b = *(float4*)&Bs[k][lane * 4];
#pragma unroll
            for (int i = 0; i < 8; i++) {
                float a = As[warp * 8 + i][k];
                acc[i][0] = fmaf(a, b.x, acc[i][0]);
                acc[i][1] = fmaf(a, b.y, acc[i][1]);
                acc[i][2] = fmaf(a, b.z, acc[i][2]);
                acc[i][3] = fmaf(a, b.w, acc[i][3]);
            }
        }
        __syncthreads();
    }

    float4 bb = make_float4(0.f, 0.f, 0.f, 0.f);
    if (MODE == 0) bb = *(const float4*)&bias[lane * 4];
#pragma unroll
    for (int i = 0; i < 8; i++) {
        int row = bm + warp * 8 + i;
        if (row < M) {
            float4 o = make_float4(acc[i][0] + bb.x, acc[i][1] + bb.y,
                                   acc[i][2] + bb.z, acc[i][3] + bb.w);
            if (MODE == 0) {
                o.x = fmaxf(o.x, 0.f); o.y = fmaxf(o.y, 0.f);
                o.z = fmaxf(o.z, 0.f); o.w = fmaxf(o.w, 0.f);
            }
            *(float4*)&C[(size_t)row * 128 + lane * 4] = o;
        }
    }
}

// ---------------- per-layer state init --------------------------------------
__global__ void init_layer_kernel() {
    int idx = blockIdx.x * blockDim.x + threadIdx.x;
    if (idx < N_NODES * HID) g_agg[idx] = 0.f;
    if (idx < N_NODES * HEADS) { g_emax[idx] = 0u; g_den[idx] = 0.f; }
}

// ---------------- attention scores per node (warp per node) ----------------
__global__ __launch_bounds__(256) void attscore_kernel(
    const float* __restrict__ att_s, const float* __restrict__ att_d)
{
    int gid = blockIdx.x * blockDim.x + threadIdx.x;
    int n = gid >> 5, lane = gid & 31;
    if (n >= N_NODES) return;
    int head = lane >> 3;
    float4 hv = *(const float4*)&g_h2[(size_t)n * 128 + lane * 4];
    float4 a  = *(const float4*)&att_s[head * 32 + (lane & 7) * 4];
    float4 b  = *(const float4*)&att_d[head * 32 + (lane & 7) * 4];
    float ps = hv.x * a.x + hv.y * a.y + hv.z * a.z + hv.w * a.w;
    float pd = hv.x * b.x + hv.y * b.y + hv.z * b.z + hv.w * b.w;
#pragma unroll
    for (int m = 1; m < 8; m <<= 1) {
        ps += __shfl_xor_sync(0xffffffffu, ps, m);
        pd += __shfl_xor_sync(0xffffffffu, pd, m);
    }
    if ((lane & 7) == 0) {
        g_asrc[n * 4 + head] = ps;
        g_adst[n * 4 + head] = pd;
    }
}

// ---------------- edge pass 1: logits + segment max -------------------------
__global__ __launch_bounds__(256) void edge_pass1_kernel(const int* __restrict__ ei)
{
    int idx = blockIdx.x * blockDim.x + threadIdx.x;
    if (idx >= ET) return;
    int s, d;
    if (idx < N_EDGES) { s = ei[idx]; d = ei[N_EDGES + idx]; }
    else               { s = d = idx - N_EDGES; }
    float4 a = *(const float4*)&g_asrc[s * 4];
    float4 b = *(const float4*)&g_adst[d * 4];
    float4 v = make_float4(a.x + b.x, a.y + b.y, a.z + b.z, a.w + b.w);
    v.x = v.x > 0.f ? v.x : NEG_SLOPE * v.x;
    v.y = v.y > 0.f ? v.y : NEG_SLOPE * v.y;
    v.z = v.z > 0.f ? v.z : NEG_SLOPE * v.z;
    v.w = v.w > 0.f ? v.w : NEG_SLOPE * v.w;
    *(float4*)&g_e[idx * 4] = v;
    atomicMax(&g_emax[d * 4 + 0], fenc(v.x));
    atomicMax(&g_emax[d * 4 + 1], fenc(v.y));
    atomicMax(&g_emax[d * 4 + 2], fenc(v.z));
    atomicMax(&g_emax[d * 4 + 3], fenc(v.w));
}

// ---------------- edge pass 2: exp + segment sum ----------------------------
__global__ __launch_bounds__(256) void edge_pass2_kernel(const int* __restrict__ ei)
{
    int idx = blockIdx.x * blockDim.x + threadIdx.x;
    if (idx >= ET) return;
    int d = (idx < N_EDGES) ? ei[N_EDGES + idx] : (idx - N_EDGES);
    float4 v = *(float4*)&g_e[idx * 4];
    uint4 mu = *(uint4*)&g_emax[d * 4];
    float4 ex = make_float4(__expf(v.x - fdec(mu.x)), __expf(v.y - fdec(mu.y)),
                            __expf(v.z - fdec(mu.z)), __expf(v.w - fdec(mu.w)));
    *(float4*)&g_e[idx * 4] = ex;
    redAdd4(&g_den[d * 4], ex);
}

// ---------------- edge pass 3: weighted aggregation (warp per edge) ---------
__global__ __launch_bounds__(256) void edge_pass3_kernel(const int* __restrict__ ei)
{
    int gid = blockIdx.x * blockDim.x + threadIdx.x;
    int e = gid >> 5, lane = gid & 31;
    if (e >= ET) return;
    int s, d;
    if (e < N_EDGES) { s = ei[e]; d = ei[N_EDGES + e]; }
    else             { s = d = e - N_EDGES; }
    float4 ex = *(const float4*)&g_e[e * 4];
    float4 dn = *(const float4*)&g_den[d * 4];
    int head = lane >> 3;
    float exh = (head == 0) ? ex.x : (head == 1) ? ex.y : (head == 2) ? ex.z : ex.w;
    float dnh = (head == 0) ? dn.x : (head == 1) ? dn.y : (head == 2) ? dn.z : dn.w;
    float alpha = exh / fmaxf(dnh, 1e-16f);
    float4 hv = *(const float4*)&g_h2[(size_t)s * 128 + lane * 4];
    float4 contrib = make_float4(alpha * hv.x, alpha * hv.y, alpha * hv.z, alpha * hv.w);
    redAdd4(&g_agg[(size_t)d * 128 + lane * 4], contrib);
}

// ---------------- node epilogue: +bias, LN, relu, +residual (warp/node) ----
__global__ __launch_bounds__(256) void node_kernel(
    const float* __restrict__ bgat, const float* __restrict__ lng,
    const float* __restrict__ lnb)
{
    int gid = blockIdx.x * blockDim.x + threadIdx.x;
    int n = gid >> 5, lane = gid & 31;
    if (n >= N_NODES) return;
    float4 v = *(const float4*)&g_agg[(size_t)n * 128 + lane * 4];
    float4 bb = *(const float4*)&bgat[lane * 4];
    v.x += bb.x; v.y += bb.y; v.z += bb.z; v.w += bb.w;
    float s = v.x + v.y + v.z + v.w;
#pragma unroll
    for (int m = 16; m; m >>= 1) s += __shfl_xor_sync(0xffffffffu, s, m);
    float mu = s * (1.f / 128.f);
    float dx = v.x - mu, dy = v.y - mu, dz = v.z - mu, dw = v.w - mu;
    float q = dx * dx + dy * dy + dz * dz + dw * dw;
#pragma unroll
    for (int m = 16; m; m >>= 1) q += __shfl_xor_sync(0xffffffffu, q, m);
    float r = rsqrtf(q * (1.f / 128.f) + LN_EPS);
    float4 g = *(const float4*)&lng[lane * 4];
    float4 b = *(const float4*)&lnb[lane * 4];
    float4 res = *(const float4*)&g_h[(size_t)n * 128 + lane * 4];
    float4 o;
    o.x = fmaxf(dx * r * g.x + b.x, 0.f) + res.x;
    o.y = fmaxf(dy * r * g.y + b.y, 0.f) + res.y;
    o.z = fmaxf(dz * r * g.z + b.z, 0.f) + res.z;
    o.w = fmaxf(dw * r * g.w + b.w, 0.f) + res.w;
    *(float4*)&g_h[(size_t)n * 128 + lane * 4] = o;
}

// ---------------- pooling ----------------------------------------------------
__global__ void pool_init_kernel() {
    int idx = blockIdx.x * blockDim.x + threadIdx.x;
    if (idx < N_GRAPHS * HID) g_psum[idx] = 0.f;
    if (idx < N_GRAPHS) g_pcnt[idx] = 0;
}

__global__ __launch_bounds__(256) void pool_acc_kernel(const int* __restrict__ batch)
{
    int gid = blockIdx.x * blockDim.x + threadIdx.x;
    int n = gid >> 5, lane = gid & 31;
    if (n >= N_NODES) return;
    int b = batch[n];
    float4 hv = *(const float4*)&g_h[(size_t)n * 128 + lane * 4];
    redAdd4(&g_psum[b * 128 + lane * 4], hv);
    if (lane == 0) atomicAdd(&g_pcnt[b], 1);
}

__global__ void pool_div_kernel(float* __restrict__ out)
{
    int idx = blockIdx.x * blockDim.x + threadIdx.x;
    if (idx >= N_GRAPHS * HID) return;
    float c = (float)g_pcnt[idx / 128];
    out[idx] = g_psum[idx] / fmaxf(c, 1.f);
}

// ---------------- launch ------------------------------------------------------
extern "C" void kernel_launch(void* const* d_in, const int* in_sizes, int n_in,
                              void* d_out, int out_size)
{
    const float* x       = (const float*)d_in[0];
    const float* W_in    = (const float*)d_in[1];
    const float* b_in    = (const float*)d_in[2];
    const float* W_gat   = (const float*)d_in[3];
    const float* att_src = (const float*)d_in[4];
    const float* att_dst = (const float*)d_in[5];
    const float* b_gat   = (const float*)d_in[6];
    const float* ln_g    = (const float*)d_in[7];
    const float* ln_b    = (const float*)d_in[8];
    const int*   ei      = (const int*)d_in[9];
    const int*   batch   = (const int*)d_in[10];
    float* out = (float*)d_out;

    const int gemm_blocks = (N_NODES + 63) / 64;       // 1563
    const int nodew_blocks = N_NODES / 8;              // 12500 (warp/node, 8 warps/blk)
    const int edge_blocks = (ET + 255) / 256;          // 6641
    const int edgew_blocks = ET / 8;                   // 212500 (warp/edge)
    const int init_blocks = (N_NODES * HID + 255) / 256;

    // input projection + relu (writes g_h)
    gemm128_kernel<0><<<gemm_blocks, 256>>>(x, W_in, b_in, N_NODES, IN_DIM);

    for (int l = 0; l < LAYERS; l++) {
        init_layer_kernel<<<init_blocks, 256>>>();
        // projection: g_h2 = g_h @ W_gat[l]
        gemm128_kernel<1><<<gemm_blocks, 256>>>(nullptr, W_gat + (size_t)l * HID * HID,
                                                nullptr, N_NODES, HID);
        attscore_kernel<<<nodew_blocks, 256>>>(att_src + l * HID, att_dst + l * HID);
        edge_pass1_kernel<<<edge_blocks, 256>>>(ei);
        edge_pass2_kernel<<<edge_blocks, 256>>>(ei);
        edge_pass3_kernel<<<edgew_blocks, 256>>>(ei);
        node_kernel<<<nodew_blocks, 256>>>(b_gat + l * HID, ln_g + l * HID, ln_b + l * HID);
    }

    pool_init_kernel<<<(N_GRAPHS * HID + 255) / 256, 256>>>();
    pool_acc_kernel<<<nodew_blocks, 256>>>(batch);
    pool_div_kernel<<<(N_GRAPHS * HID + 255) / 256, 256>>>(out);
}

// round 4
// speedup vs baseline: 1.8559x; 1.8559x over previous
#include <cuda_runtime.h>
#include <cuda_bf16.h>
#include <math.h>

#define N_NODES 100000
#define N_EDGES 1600000
#define ET      (N_EDGES + N_NODES)   // with self-loops
#define N_GRAPHS 256
#define IN_DIM  480
#define HID     128
#define HEADS   4
#define HEAD_DIM 32
#define LAYERS  3
#define NEG_SLOPE 0.2f
#define LN_EPS 1e-5f

// ---------------- scratch (device globals) ----------------------------------
__device__ float g_h   [N_NODES * HID];   // current features / residual
__device__ float g_h2  [N_NODES * HID];   // projected features per layer
__device__ float g_asrc[N_NODES * HEADS];
__device__ float g_adst[N_NODES * HEADS];
__device__ int   g_cnt [N_NODES];         // histogram, then fill cursor
__device__ int   g_rptr[N_NODES + 1];     // CSR row pointers (by dst)
__device__ int   g_srcs[ET];              // CSR: src index per edge slot
__device__ float g_psum[N_GRAPHS * HID];
__device__ int   g_pcnt[N_GRAPHS];

// sm_90+ vector reduction: one 16B L2 atomic instead of 4 scalar atomics
__device__ __forceinline__ void redAdd4(float* addr, float4 v) {
    asm volatile("red.global.add.v4.f32 [%0], {%1,%2,%3,%4};"
                 :: "l"(addr), "f"(v.x), "f"(v.y), "f"(v.z), "f"(v.w)
                 : "memory");
}

// ---------------- GEMM: C[M,128] = A[M,K] @ B[K,128] (+bias, relu) ----------
// MODE 0: A = input x, C = g_h, bias+relu.  MODE 1: A = g_h, C = g_h2, plain.
template <int MODE>
__global__ __launch_bounds__(256) void gemm128_kernel(
    const float* __restrict__ Ain, const float* __restrict__ B,
    const float* __restrict__ bias, int M, int K)
{
    const float* A = (MODE == 0) ? Ain : g_h;
    float*       C = (MODE == 0) ? g_h : g_h2;

    __shared__ float As[64][16];
    __shared__ float Bs[16][128];
    const int t = threadIdx.x;
    const int warp = t >> 5, lane = t & 31;
    const int bm = blockIdx.x * 64;

    float acc[8][4];
#pragma unroll
    for (int i = 0; i < 8; i++) { acc[i][0]=0.f; acc[i][1]=0.f; acc[i][2]=0.f; acc[i][3]=0.f; }

    for (int kt = 0; kt < K; kt += 16) {
        {
            int row = t >> 2, c4 = (t & 3) * 4;
            float4 v = make_float4(0.f, 0.f, 0.f, 0.f);
            if (bm + row < M)
                v = *(const float4*)&A[(size_t)(bm + row) * K + kt + c4];
            As[row][c4+0] = v.x; As[row][c4+1] = v.y;
            As[row][c4+2] = v.z; As[row][c4+3] = v.w;
        }
#pragma unroll
        for (int j = 0; j < 2; j++) {
            int idx = t + j * 256;
            int row = idx >> 5, c4 = (idx & 31) * 4;
            *(float4*)&Bs[row][c4] = *(const float4*)&B[(size_t)(kt + row) * 128 + c4];
        }
        __syncthreads();
#pragma unroll
        for (int k = 0; k < 16; k++) {
            float4 b = *(float4*)&Bs[k][lane * 4];
#pragma unroll
            for (int i = 0; i < 8; i++) {
                float a = As[warp * 8 + i][k];
                acc[i][0] = fmaf(a, b.x, acc[i][0]);
                acc[i][1] = fmaf(a, b.y, acc[i][1]);
                acc[i][2] = fmaf(a, b.z, acc[i][2]);
                acc[i][3] = fmaf(a, b.w, acc[i][3]);
            }
        }
        __syncthreads();
    }

    float4 bb = make_float4(0.f, 0.f, 0.f, 0.f);
    if (MODE == 0) bb = *(const float4*)&bias[lane * 4];
#pragma unroll
    for (int i = 0; i < 8; i++) {
        int row = bm + warp * 8 + i;
        if (row < M) {
            float4 o = make_float4(acc[i][0] + bb.x, acc[i][1] + bb.y,
                                   acc[i][2] + bb.z, acc[i][3] + bb.w);
            if (MODE == 0) {
                o.x = fmaxf(o.x, 0.f); o.y = fmaxf(o.y, 0.f);
                o.z = fmaxf(o.z, 0.f); o.w = fmaxf(o.w, 0.f);
            }
            *(float4*)&C[(size_t)row * 128 + lane * 4] = o;
        }
    }
}

// ---------------- CSR build (once per call) ---------------------------------
__global__ void csr_init_kernel() {
    int i = blockIdx.x * blockDim.x + threadIdx.x;
    if (i < N_NODES) g_cnt[i] = 1;   // self-loop occupies slot 0
}

__global__ void csr_hist_kernel(const int* __restrict__ ei) {
    int e = blockIdx.x * blockDim.x + threadIdx.x;
    if (e < N_EDGES) atomicAdd(&g_cnt[ei[N_EDGES + e]], 1);
}

// single-block exclusive scan of g_cnt -> g_rptr
__global__ __launch_bounds__(1024) void csr_scan_kernel() {
    __shared__ int sm[1024];
    const int T = 1024;
    const int CH = (N_NODES + T - 1) / T;   // 98
    int t = threadIdx.x;
    int base = t * CH;
    int hi = min(base + CH, N_NODES);
    int sum = 0;
    for (int i = base; i < hi; i++) sum += g_cnt[i];
    sm[t] = sum;
    __syncthreads();
    // Hillis-Steele inclusive scan
    for (int o = 1; o < T; o <<= 1) {
        int v = (t >= o) ? sm[t - o] : 0;
        __syncthreads();
        sm[t] += v;
        __syncthreads();
    }
    int run = (t == 0) ? 0 : sm[t - 1];   // exclusive prefix for this chunk
    for (int i = base; i < hi; i++) { g_rptr[i] = run; run += g_cnt[i]; }
    if (t == 0) g_rptr[N_NODES] = ET;
}

__global__ void csr_self_kernel() {
    int i = blockIdx.x * blockDim.x + threadIdx.x;
    if (i < N_NODES) { g_srcs[g_rptr[i]] = i; g_cnt[i] = 1; }
}

__global__ void csr_fill_kernel(const int* __restrict__ ei) {
    int e = blockIdx.x * blockDim.x + threadIdx.x;
    if (e >= N_EDGES) return;
    int d = ei[N_EDGES + e];
    int p = g_rptr[d] + atomicAdd(&g_cnt[d], 1);
    g_srcs[p] = ei[e];
}

// ---------------- attention scores per node (warp per node) ----------------
__global__ __launch_bounds__(256) void attscore_kernel(
    const float* __restrict__ att_s, const float* __restrict__ att_d)
{
    int gid = blockIdx.x * blockDim.x + threadIdx.x;
    int n = gid >> 5, lane = gid & 31;
    if (n >= N_NODES) return;
    int head = lane >> 3;
    float4 hv = *(const float4*)&g_h2[(size_t)n * 128 + lane * 4];
    float4 a  = *(const float4*)&att_s[head * 32 + (lane & 7) * 4];
    float4 b  = *(const float4*)&att_d[head * 32 + (lane & 7) * 4];
    float ps = hv.x * a.x + hv.y * a.y + hv.z * a.z + hv.w * a.w;
    float pd = hv.x * b.x + hv.y * b.y + hv.z * b.z + hv.w * b.w;
#pragma unroll
    for (int m = 1; m < 8; m <<= 1) {
        ps += __shfl_xor_sync(0xffffffffu, ps, m);
        pd += __shfl_xor_sync(0xffffffffu, pd, m);
    }
    if ((lane & 7) == 0) {
        g_asrc[n * 4 + head] = ps;
        g_adst[n * 4 + head] = pd;
    }
}

__device__ __forceinline__ float leaky(float v) {
    return v > 0.f ? v : NEG_SLOPE * v;
}

// ---------------- fused GAT layer: softmax + aggregate + LN (warp/node) ----
__global__ __launch_bounds__(256) void gat_fused_kernel(
    const float* __restrict__ bgat, const float* __restrict__ lng,
    const float* __restrict__ lnb)
{
    int gid = blockIdx.x * blockDim.x + threadIdx.x;
    int n = gid >> 5, lane = gid & 31;
    if (n >= N_NODES) return;
    const int head = lane >> 3;
    const int beg = g_rptr[n], end = g_rptr[n + 1];

    float4 ad = *(const float4*)&g_adst[n * 4];   // uniform across warp

    // ---- pass A: per-head max over incident edges (lanes parallel) ----
    float4 mx = make_float4(-1e30f, -1e30f, -1e30f, -1e30f);
    for (int k = beg + lane; k < end; k += 32) {
        int s = g_srcs[k];
        float4 a = *(const float4*)&g_asrc[s * 4];
        mx.x = fmaxf(mx.x, leaky(a.x + ad.x));
        mx.y = fmaxf(mx.y, leaky(a.y + ad.y));
        mx.z = fmaxf(mx.z, leaky(a.z + ad.z));
        mx.w = fmaxf(mx.w, leaky(a.w + ad.w));
    }
#pragma unroll
    for (int o = 16; o; o >>= 1) {
        mx.x = fmaxf(mx.x, __shfl_xor_sync(0xffffffffu, mx.x, o));
        mx.y = fmaxf(mx.y, __shfl_xor_sync(0xffffffffu, mx.y, o));
        mx.z = fmaxf(mx.z, __shfl_xor_sync(0xffffffffu, mx.z, o));
        mx.w = fmaxf(mx.w, __shfl_xor_sync(0xffffffffu, mx.w, o));
    }
    const float mh  = (head == 0) ? mx.x : (head == 1) ? mx.y : (head == 2) ? mx.z : mx.w;
    const float adh = (head == 0) ? ad.x : (head == 1) ? ad.y : (head == 2) ? ad.z : ad.w;

    // ---- pass B: accumulate exp-weighted features (lanes = 128 features) ----
    float4 acc = make_float4(0.f, 0.f, 0.f, 0.f);
    float den = 0.f;
    int k = beg;
    for (; k + 2 <= end; k += 2) {
        int s0 = g_srcs[k], s1 = g_srcs[k + 1];
        float as0 = g_asrc[s0 * 4 + head];
        float as1 = g_asrc[s1 * 4 + head];
        float4 hv0 = *(const float4*)&g_h2[(size_t)s0 * 128 + lane * 4];
        float4 hv1 = *(const float4*)&g_h2[(size_t)s1 * 128 + lane * 4];
        float ex0 = __expf(leaky(as0 + adh) - mh);
        float ex1 = __expf(leaky(as1 + adh) - mh);
        den += ex0 + ex1;
        acc.x = fmaf(ex0, hv0.x, fmaf(ex1, hv1.x, acc.x));
        acc.y = fmaf(ex0, hv0.y, fmaf(ex1, hv1.y, acc.y));
        acc.z = fmaf(ex0, hv0.z, fmaf(ex1, hv1.z, acc.z));
        acc.w = fmaf(ex0, hv0.w, fmaf(ex1, hv1.w, acc.w));
    }
    if (k < end) {
        int s0 = g_srcs[k];
        float as0 = g_asrc[s0 * 4 + head];
        float4 hv0 = *(const float4*)&g_h2[(size_t)s0 * 128 + lane * 4];
        float ex0 = __expf(leaky(as0 + adh) - mh);
        den += ex0;
        acc.x = fmaf(ex0, hv0.x, acc.x);
        acc.y = fmaf(ex0, hv0.y, acc.y);
        acc.z = fmaf(ex0, hv0.z, acc.z);
        acc.w = fmaf(ex0, hv0.w, acc.w);
    }
    float inv = 1.f / fmaxf(den, 1e-16f);

    // ---- fused epilogue: +bias, LayerNorm, ReLU, +residual ----
    float4 bb = *(const float4*)&bgat[lane * 4];
    float4 v = make_float4(acc.x * inv + bb.x, acc.y * inv + bb.y,
                           acc.z * inv + bb.z, acc.w * inv + bb.w);
    float s = v.x + v.y + v.z + v.w;
#pragma unroll
    for (int m = 16; m; m >>= 1) s += __shfl_xor_sync(0xffffffffu, s, m);
    float mu = s * (1.f / 128.f);
    float dx = v.x - mu, dy = v.y - mu, dz = v.z - mu, dw = v.w - mu;
    float q = dx * dx + dy * dy + dz * dz + dw * dw;
#pragma unroll
    for (int m = 16; m; m >>= 1) q += __shfl_xor_sync(0xffffffffu, q, m);
    float r = rsqrtf(q * (1.f / 128.f) + LN_EPS);
    float4 g = *(const float4*)&lng[lane * 4];
    float4 b = *(const float4*)&lnb[lane * 4];
    float4 res = *(const float4*)&g_h[(size_t)n * 128 + lane * 4];
    float4 o;
    o.x = fmaxf(dx * r * g.x + b.x, 0.f) + res.x;
    o.y = fmaxf(dy * r * g.y + b.y, 0.f) + res.y;
    o.z = fmaxf(dz * r * g.z + b.z, 0.f) + res.z;
    o.w = fmaxf(dw * r * g.w + b.w, 0.f) + res.w;
    *(float4*)&g_h[(size_t)n * 128 + lane * 4] = o;
}

// ---------------- pooling ----------------------------------------------------
__global__ void pool_init_kernel() {
    int idx = blockIdx.x * blockDim.x + threadIdx.x;
    if (idx < N_GRAPHS * HID) g_psum[idx] = 0.f;
    if (idx < N_GRAPHS) g_pcnt[idx] = 0;
}

__global__ __launch_bounds__(256) void pool_acc_kernel(const int* __restrict__ batch)
{
    int gid = blockIdx.x * blockDim.x + threadIdx.x;
    int n = gid >> 5, lane = gid & 31;
    if (n >= N_NODES) return;
    int b = batch[n];
    float4 hv = *(const float4*)&g_h[(size_t)n * 128 + lane * 4];
    redAdd4(&g_psum[b * 128 + lane * 4], hv);
    if (lane == 0) atomicAdd(&g_pcnt[b], 1);
}

__global__ void pool_div_kernel(float* __restrict__ out)
{
    int idx = blockIdx.x * blockDim.x + threadIdx.x;
    if (idx >= N_GRAPHS * HID) return;
    float c = (float)g_pcnt[idx / 128];
    out[idx] = g_psum[idx] / fmaxf(c, 1.f);
}

// ---------------- launch ------------------------------------------------------
extern "C" void kernel_launch(void* const* d_in, const int* in_sizes, int n_in,
                              void* d_out, int out_size)
{
    const float* x       = (const float*)d_in[0];
    const float* W_in    = (const float*)d_in[1];
    const float* b_in    = (const float*)d_in[2];
    const float* W_gat   = (const float*)d_in[3];
    const float* att_src = (const float*)d_in[4];
    const float* att_dst = (const float*)d_in[5];
    const float* b_gat   = (const float*)d_in[6];
    const float* ln_g    = (const float*)d_in[7];
    const float* ln_b    = (const float*)d_in[8];
    const int*   ei      = (const int*)d_in[9];
    const int*   batch   = (const int*)d_in[10];
    float* out = (float*)d_out;

    const int gemm_blocks  = (N_NODES + 63) / 64;
    const int nodew_blocks = N_NODES / 8;              // warp per node, 8 warps/blk
    const int node_blocks  = (N_NODES + 255) / 256;
    const int edge_blocks  = (N_EDGES + 255) / 256;

    // CSR build (by destination), self-loop in slot 0 of each row
    csr_init_kernel<<<node_blocks, 256>>>();
    csr_hist_kernel<<<edge_blocks, 256>>>(ei);
    csr_scan_kernel<<<1, 1024>>>();
    csr_self_kernel<<<node_blocks, 256>>>();
    csr_fill_kernel<<<edge_blocks, 256>>>(ei);

    // input projection + relu (writes g_h)
    gemm128_kernel<0><<<gemm_blocks, 256>>>(x, W_in, b_in, N_NODES, IN_DIM);

    for (int l = 0; l < LAYERS; l++) {
        gemm128_kernel<1><<<gemm_blocks, 256>>>(nullptr, W_gat + (size_t)l * HID * HID,
                                                nullptr, N_NODES, HID);
        attscore_kernel<<<nodew_blocks, 256>>>(att_src + l * HID, att_dst + l * HID);
        gat_fused_kernel<<<nodew_blocks, 256>>>(b_gat + l * HID, ln_g + l * HID, ln_b + l * HID);
    }

    pool_init_kernel<<<(N_GRAPHS * HID + 255) / 256, 256>>>();
    pool_acc_kernel<<<nodew_blocks, 256>>>(batch);
    pool_div_kernel<<<(N_GRAPHS * HID + 255) / 256, 256>>>(out);
}